// round 13
// baseline (speedup 1.0000x reference)
#include <cuda_runtime.h>
#include <cuda_fp16.h>
#include <stdint.h>

#define RES 512
#define PR  514                    // padded texel range 0..513 per axis
#define CH  32
#define NENT 257                   // pair-entries per row (texels 0..514)
#define ROW_HALVES (NENT * 64)     // 16448 halves = 32896 B per row
#define COPY_HALVES ((size_t)PR * ROW_HALVES)

// Parity-duplicated, zero-padded planes, fp16:
//   g_C[p*2+0] (copy E): entry k = texels (2k,   2k+1)   -> for even ix
//   g_C[p*2+1] (copy O): entry k = texels (2k+1, 2k+2)   -> for odd  ix
// One entry = 128B aligned = both x corners of a bilinear pair in ONE line.
__device__ __align__(128) __half g_C[6][COPY_HALVES];

// ---------------------------------------------------------------------------
// Prep: transpose (C,H,W) fp32 -> both parity copies, fp16, padded.
// Ring/pad zeroing folded into blockIdx.y==0 blocks (threads 128..160).
// grid = (RES, RES/32, 3), block = (32, 8).
// ---------------------------------------------------------------------------
__global__ __launch_bounds__(256) void triplane_prep_kernel(
    const float* __restrict__ t_xy,
    const float* __restrict__ t_yz,
    const float* __restrict__ t_zx)
{
    __shared__ float tile[32][33];   // [channel][x-in-tile]

    const int y  = blockIdx.x;
    const int x0 = blockIdx.y * 32;
    const int p  = blockIdx.z;
    const int tx = threadIdx.x;      // 0..31
    const int ty = threadIdx.y;      // 0..7
    const int tid = ty * 32 + tx;

    const float* src = (p == 0) ? t_xy : (p == 1) ? t_yz : t_zx;
    const float* sp = src + y * RES + x0 + tx;

#pragma unroll
    for (int i = 0; i < 4; ++i) {
        const int c = ty + 8 * i;
        tile[c][tx] = sp[c * (RES * RES)];   // coalesced, MLP=4
    }

    // ---- Zero the pad regions (16416 16B-segs per plane, 33 per y-block) ----
    // Layout of zero tasks per plane:
    //   [0, 8224):  full rows 0 and 513 in both copies (4 grps x 257 ent x 8)
    //   [8224,16416): per interior row r=1..512: E ent0 lo (4), E ent256 hi (4),
    //                 O ent256 full (8)  -> 16 segs per row
    if (blockIdx.y == 0) {
        const int t = tid - 128;
        if (t >= 0 && t < 33) {
            const int segID = y * 33 + t;
            if (segID < 16416) {
                int copy, row, entry, sub;
                if (segID < 8224) {
                    const int grp    = segID / 2056;   // 0..3
                    const int within = segID % 2056;
                    row   = (grp < 2) ? 0 : (PR - 1);
                    copy  = grp & 1;
                    entry = within >> 3;
                    sub   = (within & 7) * 8;
                } else {
                    const int idx2 = segID - 8224;
                    row = idx2 / 16 + 1;
                    const int t16 = idx2 % 16;
                    if (t16 < 4)      { copy = 0; entry = 0;        sub = t16 * 8; }
                    else if (t16 < 8) { copy = 0; entry = NENT - 1; sub = 32 + (t16 - 4) * 8; }
                    else              { copy = 1; entry = NENT - 1; sub = (t16 - 8) * 8; }
                }
                *(uint4*)(g_C[p * 2 + copy] + (size_t)row * ROW_HALVES
                          + entry * 64 + sub) = make_uint4(0u, 0u, 0u, 0u);
            }
        }
    }
    __syncthreads();

    if (tid < 128) {
        const int xx  = tid >> 2;        // texel within tile (0..31)
        const int seg = tid & 3;         // 16B segment of the 64B texel

        uint4 v;
#pragma unroll
        for (int j = 0; j < 4; ++j) {
            const int c = seg * 8 + 2 * j;
            ((__half2*)&v)[j] = __floats2half2_rn(tile[c][xx], tile[c + 1][xx]);
        }

        const int px = x0 + xx + 1;             // padded texel x in 1..512
        const size_t rowb = (size_t)(y + 1) * ROW_HALVES;

        // copy E: entry px>>1, slot px&1
        {
            const int k = px >> 1, slot = px & 1;
            *(uint4*)(g_C[p * 2] + rowb + k * 64 + slot * 32 + seg * 8) = v;
        }
        // copy O: entry (px-1)>>1, slot (px&1)^1   (px >= 1 always here)
        {
            const int k = (px - 1) >> 1, slot = (px & 1) ^ 1;
            *(uint4*)(g_C[p * 2 + 1] + rowb + k * 64 + slot * 32 + seg * 8) = v;
        }
    }
}

// ---------------------------------------------------------------------------
// Sampling: 8 lanes per point (xsel = s>>2 picks x corner, chunk = s&3 picks
// 8 channels). Parity copy selected by ix&1 -> EVERY gather is exactly one
// 128B-aligned line: 6 L1 wavefronts per point (was 9.25). half2 math e2e.
// ---------------------------------------------------------------------------
__global__ __launch_bounds__(256) void triplane_sample_kernel(
    const float* __restrict__ xyz,
    float* __restrict__ out,
    int npts)
{
    const int gtid  = blockIdx.x * blockDim.x + threadIdx.x;
    const int pid   = gtid >> 3;
    const int s     = gtid & 7;
    const int chunk = s & 3;
    const int xsel  = s >> 2;

    // Warp-cooperative coord load: warp's 4 points need 12 floats (one line).
    const int lane = threadIdx.x & 31;
    const int wbase_pt = (blockIdx.x * blockDim.x + (threadIdx.x & ~31)) >> 3;
    float cv = 0.f;
    {
        const int ci = wbase_pt * 3 + lane;
        if (lane < 12 && ci < npts * 3) cv = __ldg(xyz + ci);
    }
    const int pg3 = (lane >> 3) * 3;
    const float cx = __shfl_sync(0xffffffffu, cv, pg3 + 0);
    const float cy = __shfl_sync(0xffffffffu, cv, pg3 + 1);
    const float cz = __shfl_sync(0xffffffffu, cv, pg3 + 2);

    if (pid >= npts) return;

    // f_xy: (X, Y)   f_yz: (Y, Z)   f_zx: (Z, X)
    const float cA[3] = {cx, cy, cz};   // W coordinate
    const float cB[3] = {cy, cz, cx};   // H coordinate

    const int laneoff = s * 8;          // this lane's 16B seg within the line

    __half2 acc[4];
    const __half2 hz = __float2half2_rn(0.f);
#pragma unroll
    for (int j = 0; j < 4; ++j) acc[j] = hz;

#pragma unroll
    for (int p = 0; p < 3; ++p) {
        // padded pixel coord = 256*c + 256.5; c in [-1,1) -> [0.5, 512.5):
        // floor indices in [0,512], no clamps, no masks.
        const float xf = fmaf(cA[p], 256.0f, 256.5f);
        const float yf = fmaf(cB[p], 256.0f, 256.5f);

        const float x0f = floorf(xf);
        const float y0f = floorf(yf);
        const float wx1 = xf - x0f;
        const float wy1 = yf - y0f;

        const int ixp = (int)x0f;       // 0..512
        const int iyp = (int)y0f;       // 0..512

        const float wxl = xsel ? wx1 : (1.0f - wx1);
        const __half2 w0h = __float2half2_rn((1.0f - wy1) * wxl);
        const __half2 w1h = __float2half2_rn(wy1 * wxl);

        // parity copy: the (ixp, ixp+1) pair is one aligned 128B entry
        const __half* cb = g_C[p * 2 + (ixp & 1)];
        const uint32_t off = (uint32_t)iyp * ROW_HALVES
                           + (uint32_t)(ixp >> 1) * 64 + laneoff;

        const uint4 v0 = __ldg((const uint4*)(cb + off));
        const uint4 v1 = __ldg((const uint4*)(cb + off + ROW_HALVES));

        const __half2* h0 = (const __half2*)&v0;
        const __half2* h1 = (const __half2*)&v1;
#pragma unroll
        for (int j = 0; j < 4; ++j) {
            acc[j] = __hfma2(h0[j], w0h, acc[j]);
            acc[j] = __hfma2(h1[j], w1h, acc[j]);
        }
    }

    // Combine the two x-corner partial sums (lane s <-> lane s^4) in half2.
#pragma unroll
    for (int j = 0; j < 4; ++j) {
        const uint32_t o = __shfl_xor_sync(0xffffffffu,
                                           *(const uint32_t*)&acc[j], 4);
        acc[j] = __hadd2(acc[j], *(const __half2*)&o);
    }

    // Convert to fp32 once and store. xsel=0 -> floats 0-3 of the chunk,
    // xsel=1 -> floats 4-7. Warp covers 512B contiguous.
    const float2 fa = __half22float2(acc[xsel ? 2 : 0]);
    const float2 fb = __half22float2(acc[xsel ? 3 : 1]);
    *(float4*)(out + (size_t)pid * CH + chunk * 8 + xsel * 4) =
        make_float4(fa.x, fa.y, fb.x, fb.y);
}

// ---------------------------------------------------------------------------
// kernel_launch
// inputs: xyz [N*3], T_xy, T_yz, T_zx [1*32*512*512] fp32 ; output [N*32] fp32
// ---------------------------------------------------------------------------
extern "C" void kernel_launch(void* const* d_in, const int* in_sizes, int n_in,
                              void* d_out, int out_size)
{
    const float* xyz  = (const float*)d_in[0];
    const float* t_xy = (const float*)d_in[1];
    const float* t_yz = (const float*)d_in[2];
    const float* t_zx = (const float*)d_in[3];
    float* out = (float*)d_out;

    const int npts = in_sizes[0] / 3;

    // 1) transpose + fp16 convert into both parity copies + pad zeroing
    dim3 tgrid(RES, RES / 32, 3);
    dim3 tblock(32, 8);
    triplane_prep_kernel<<<tgrid, tblock>>>(t_xy, t_yz, t_zx);

    // 2) sample: 8 threads per point
    const long long total = (long long)npts * 8;
    const int block = 256;
    const int grid = (int)((total + block - 1) / block);
    triplane_sample_kernel<<<grid, block>>>(xyz, out, npts);
}

// round 15
// speedup vs baseline: 1.5411x; 1.5411x over previous
#include <cuda_runtime.h>
#include <cuda_fp16.h>
#include <stdint.h>

#define RES 512
#define PR  514           // padded resolution: 1-texel zero ring
#define CH  32
#define PLANE_PAD_ELEMS (PR * PR * CH)

// Zero-padded (H, W, C) fp16 planes. Texel = 32 halves = 64B.
// Interior texel (y, x) lives at padded coords (y+1, x+1).
__device__ __align__(128) __half g_TP[3][PLANE_PAD_ELEMS];

// ---------------------------------------------------------------------------
// Prep: transpose (C,H,W) fp32 -> padded (H,W,C) fp16, border-ring zeroing
// folded into the blockIdx.y==0 blocks. grid=(RES, RES/32, 3), block=(32,8).
// ---------------------------------------------------------------------------
__global__ __launch_bounds__(256) void triplane_prep_kernel(
    const float* __restrict__ t_xy,
    const float* __restrict__ t_yz,
    const float* __restrict__ t_zx)
{
    __shared__ float tile[32][33];   // [channel][x-in-tile]

    const int y  = blockIdx.x;
    const int x0 = blockIdx.y * 32;
    const int p  = blockIdx.z;
    const int tx = threadIdx.x;      // 0..31
    const int ty = threadIdx.y;      // 0..7
    const int tid = ty * 32 + tx;

    const float* src = (p == 0) ? t_xy : (p == 1) ? t_yz : t_zx;
    const float* sp = src + y * RES + x0 + tx;

#pragma unroll
    for (int i = 0; i < 4; ++i) {
        const int c = ty + 8 * i;
        tile[c][tx] = sp[c * (RES * RES)];   // coalesced, MLP=4
    }

    // Border zeroing: 2052 ring texels/plane spread over the 512 y-blocks.
    if (blockIdx.y == 0) {
        const int nt = (y == RES - 1) ? 32 : 16;
        if (tid < nt) {
            const int b   = 4 * y + (tid >> 2);   // ring texel index < 2052
            const int seg = tid & 3;
            int by, bx;
            if (b < PR)                 { by = 0;                    bx = b; }
            else if (b < 2 * PR)        { by = PR - 1;               bx = b - PR; }
            else if (b < 2 * PR + RES)  { by = b - 2 * PR + 1;       bx = 0; }
            else                        { by = b - (2 * PR + RES) + 1; bx = PR - 1; }
            *(uint4*)(g_TP[p] + ((size_t)by * PR + bx) * CH + seg * 8) =
                make_uint4(0u, 0u, 0u, 0u);
        }
    }
    __syncthreads();

    if (tid < 128) {
        const int xx  = tid >> 2;        // texel within tile (0..31)
        const int seg = tid & 3;         // 16B segment of the 64B texel

        uint4 v;
#pragma unroll
        for (int j = 0; j < 4; ++j) {
            const int c = seg * 8 + 2 * j;
            ((__half2*)&v)[j] = __floats2half2_rn(tile[c][xx], tile[c + 1][xx]);
        }
        *(uint4*)(g_TP[p] + ((size_t)(y + 1) * PR + (x0 + xx + 1)) * CH + seg * 8) = v;
    }
}

// ---------------------------------------------------------------------------
// Cache-policy memory helpers (legal sm_103 encodings).
// ---------------------------------------------------------------------------
// Per-thread L2 evict_last policy descriptor.
__device__ __forceinline__ uint64_t mk_evict_last_policy()
{
    uint64_t pol;
    asm("createpolicy.fractional.L2::evict_last.b64 %0, 1.0;" : "=l"(pol));
    return pol;
}
// Plane gather: read-only + L2 cache-hint (evict_last policy).
__device__ __forceinline__ uint4 ldg_el(const __half* p, uint64_t pol)
{
    uint4 v;
    asm volatile("ld.global.nc.L2::cache_hint.v4.u32 {%0,%1,%2,%3}, [%4], %5;"
                 : "=r"(v.x), "=r"(v.y), "=r"(v.z), "=r"(v.w)
                 : "l"(p), "l"(pol));
    return v;
}
// Output store: streaming (evict-first) so the 256MB write stream doesn't
// evict plane lines from L2.
__device__ __forceinline__ void stg_cs(float* p, float4 v)
{
    asm volatile("st.global.cs.v4.f32 [%0], {%1,%2,%3,%4};"
                 :: "l"(p), "f"(v.x), "f"(v.y), "f"(v.z), "f"(v.w)
                 : "memory");
}

// ---------------------------------------------------------------------------
// Sampling: 8 lanes per point (xsel = s>>2 picks x corner, chunk = s&3 picks
// 8 channels). Padded planes -> no border math. half2 accumulation e2e.
// R12 structure exactly; only the cache policies differ.
// ---------------------------------------------------------------------------
__global__ __launch_bounds__(256) void triplane_sample_kernel(
    const float* __restrict__ xyz,
    float* __restrict__ out,
    int npts)
{
    const int gtid  = blockIdx.x * blockDim.x + threadIdx.x;
    const int pid   = gtid >> 3;
    const int s     = gtid & 7;
    const int chunk = s & 3;
    const int xsel  = s >> 2;

    // Warp-cooperative coord load: warp's 4 points need 12 floats (one line).
    const int lane = threadIdx.x & 31;
    const int wbase_pt = (blockIdx.x * blockDim.x + (threadIdx.x & ~31)) >> 3;
    float cv = 0.f;
    {
        const int ci = wbase_pt * 3 + lane;
        if (lane < 12 && ci < npts * 3) cv = __ldg(xyz + ci);
    }
    const int pg3 = (lane >> 3) * 3;
    const float cx = __shfl_sync(0xffffffffu, cv, pg3 + 0);
    const float cy = __shfl_sync(0xffffffffu, cv, pg3 + 1);
    const float cz = __shfl_sync(0xffffffffu, cv, pg3 + 2);

    if (pid >= npts) return;

    const uint64_t pol = mk_evict_last_policy();

    // f_xy: (X, Y)   f_yz: (Y, Z)   f_zx: (Z, X)
    const float cA[3] = {cx, cy, cz};   // W coordinate
    const float cB[3] = {cy, cz, cx};   // H coordinate

    const int laneoff = chunk * 8;      // this lane's 8-channel offset (halves)

    __half2 acc[4];
    const __half2 hz = __float2half2_rn(0.f);
#pragma unroll
    for (int j = 0; j < 4; ++j) acc[j] = hz;

#pragma unroll
    for (int p = 0; p < 3; ++p) {
        // padded pixel coord = 256*c + 256.5; c in [-1,1) -> [0.5, 512.5):
        // floor indices in [0,512], no clamps, no masks.
        const float xf = fmaf(cA[p], 256.0f, 256.5f);
        const float yf = fmaf(cB[p], 256.0f, 256.5f);

        const float x0f = floorf(xf);
        const float y0f = floorf(yf);
        const float wx1 = xf - x0f;
        const float wy1 = yf - y0f;

        const int ixp = (int)x0f;
        const int iyp = (int)y0f;

        const float wxl = xsel ? wx1 : (1.0f - wx1);
        const __half2 w0h = __float2half2_rn((1.0f - wy1) * wxl);
        const __half2 w1h = __float2half2_rn(wy1 * wxl);

        const __half* t = g_TP[p]
                        + (size_t)(iyp * PR + ixp + xsel) * CH + laneoff;
        const uint4 v0 = ldg_el(t, pol);
        const uint4 v1 = ldg_el(t + PR * CH, pol);

        const __half2* h0 = (const __half2*)&v0;
        const __half2* h1 = (const __half2*)&v1;
#pragma unroll
        for (int j = 0; j < 4; ++j) {
            acc[j] = __hfma2(h0[j], w0h, acc[j]);
            acc[j] = __hfma2(h1[j], w1h, acc[j]);
        }
    }

    // Combine the two x-corner partial sums (lane s <-> lane s^4) in half2.
#pragma unroll
    for (int j = 0; j < 4; ++j) {
        const uint32_t o = __shfl_xor_sync(0xffffffffu,
                                           *(const uint32_t*)&acc[j], 4);
        acc[j] = __hadd2(acc[j], *(const __half2*)&o);
    }

    // Convert to fp32 once and store (streaming). xsel=0 -> floats 0-3 of the
    // chunk, xsel=1 -> floats 4-7. Warp covers 512B contiguous.
    const float2 fa = __half22float2(acc[xsel ? 2 : 0]);
    const float2 fb = __half22float2(acc[xsel ? 3 : 1]);
    stg_cs(out + (size_t)pid * CH + chunk * 8 + xsel * 4,
           make_float4(fa.x, fa.y, fb.x, fb.y));
}

// ---------------------------------------------------------------------------
// kernel_launch
// inputs: xyz [N*3], T_xy, T_yz, T_zx [1*32*512*512] fp32 ; output [N*32] fp32
// ---------------------------------------------------------------------------
extern "C" void kernel_launch(void* const* d_in, const int* in_sizes, int n_in,
                              void* d_out, int out_size)
{
    const float* xyz  = (const float*)d_in[0];
    const float* t_xy = (const float*)d_in[1];
    const float* t_yz = (const float*)d_in[2];
    const float* t_zx = (const float*)d_in[3];
    float* out = (float*)d_out;

    const int npts = in_sizes[0] / 3;

    // 1) transpose + fp16 convert + border zeroing, one launch
    dim3 tgrid(RES, RES / 32, 3);
    dim3 tblock(32, 8);
    triplane_prep_kernel<<<tgrid, tblock>>>(t_xy, t_yz, t_zx);

    // 2) sample: 8 threads per point
    const long long total = (long long)npts * 8;
    const int block = 256;
    const int grid = (int)((total + block - 1) / block);
    triplane_sample_kernel<<<grid, block>>>(xyz, out, npts);
}